// round 15
// baseline (speedup 1.0000x reference)
#include <cuda_runtime.h>

#define Bv 32
#define Tv 1000
#define DINv 64
#define Hv 1024

#define NBG 4
#define NJG 32
#define BTILE 8
#define JTILE 32
#define NTHREADS 256
#define GRID (NBG * NJG)     // 128 CTAs, 1/SM

#define WS 36                // W row stride (floats)
#define HS 10                // h row stride (floats)
#define RS 296               // red slice stride (floats): 1184B -> 4-wf STS.128
#define NMS 32               // merged k-slices (64 pre-merged in-warp to 32)
#define KPT 16               // k per thread

__device__ unsigned g_flag[NBG][NJG][32];      // per-producer flags, 128B apart
__device__ float h_bufT[2][NBG][Hv * HS];      // h state, pre-laid-out [k*10+b]

struct Smem {
    float Ws[Hv * WS];                  // 147456 B
    float h_s[Hv * HS];                 //  40960 B (chunk w touched only by warp w)
    float red[NMS * RS];                //  37888 B (separate: no union, no sync C)
};
// total = 226304 B < 232448 B

struct UinSmem {
    float2 xs2[DINv * 65];
    float  wis[DINv * 130];
};

// ---------------------------------------------------------------------------
// Phase 1: u_in = x @ W_in^T + b -> out ; resets flags. 64 rows/block.
// ---------------------------------------------------------------------------
__global__ void __launch_bounds__(256)
esn_uin_kernel(const float* __restrict__ x, const float* __restrict__ Wiw,
               const float* __restrict__ Wib, float* __restrict__ out)
{
    extern __shared__ unsigned char usmem_raw[];
    UinSmem& us = *reinterpret_cast<UinSmem*>(usmem_raw);

    if (blockIdx.x == 0 && threadIdx.x < NBG * NJG)
        g_flag[threadIdx.x >> 5][threadIdx.x & 31][0] = 0u;

    const int tid = threadIdx.x;
    const int R0  = blockIdx.x * 64;

    {
        const int kk = tid & 63;
        for (int r = tid >> 6; r < 64; r += 4) {
            float v = x[(size_t)(R0 + r) * DINv + kk];
            us.xs2[kk * 65 + r] = make_float2(v, v);
        }
    }

    const int jp = tid & 63;
    const int rq = tid >> 6;
    const unsigned wis_s = (unsigned)__cvta_generic_to_shared(us.wis);
    const unsigned xs_s  = (unsigned)__cvta_generic_to_shared(us.xs2);

    for (int jc = 0; jc < 8; ++jc) {
        __syncthreads();
        for (int idx = tid; idx < 128 * DINv; idx += 256) {
            int jj = idx >> 6, kk = idx & 63;
            us.wis[kk * 130 + jj] = Wiw[(jc * 128 + jj) * DINv + kk];
        }
        __syncthreads();

        float2 bias2 = *(const float2*)&Wib[jc * 128 + 2 * jp];
        unsigned long long b2;
        asm("mov.b64 %0,{%1,%2};" : "=l"(b2) : "f"(bias2.x), "f"(bias2.y));

        #pragma unroll
        for (int rg = 0; rg < 4; ++rg) {
            unsigned long long acc[4];
            #pragma unroll
            for (int r = 0; r < 4; ++r) acc[r] = b2;

            unsigned wa = wis_s + (2 * jp) * 4;
            unsigned xa = xs_s + (rg * 16 + rq * 4) * 8;
            #pragma unroll 8
            for (int k = 0; k < DINv; ++k) {
                unsigned long long w01, x0, x1, x2, x3;
                asm("ld.shared.u64 %0,[%1];" : "=l"(w01) : "r"(wa));
                asm("ld.shared.u64 %0,[%1];" : "=l"(x0) : "r"(xa));
                asm("ld.shared.u64 %0,[%1+8];" : "=l"(x1) : "r"(xa));
                asm("ld.shared.u64 %0,[%1+16];" : "=l"(x2) : "r"(xa));
                asm("ld.shared.u64 %0,[%1+24];" : "=l"(x3) : "r"(xa));
                asm("fma.rn.f32x2 %0,%1,%2,%0;" : "+l"(acc[0]) : "l"(w01), "l"(x0));
                asm("fma.rn.f32x2 %0,%1,%2,%0;" : "+l"(acc[1]) : "l"(w01), "l"(x1));
                asm("fma.rn.f32x2 %0,%1,%2,%0;" : "+l"(acc[2]) : "l"(w01), "l"(x2));
                asm("fma.rn.f32x2 %0,%1,%2,%0;" : "+l"(acc[3]) : "l"(w01), "l"(x3));
                wa += 130 * 4;
                xa += 65 * 8;
            }

            #pragma unroll
            for (int r = 0; r < 4; ++r) {
                float fx, fy;
                asm("mov.b64 {%0,%1},%2;" : "=f"(fx), "=f"(fy) : "l"(acc[r]));
                float2* op = (float2*)&out[(size_t)(R0 + rg * 16 + rq * 4 + r) * Hv
                                           + jc * 128 + 2 * jp];
                *op = make_float2(fx, fy);
            }
        }
    }
}

// ---------------------------------------------------------------------------
// Phase 2: persistent scan. Per-warp flags + per-warp chunk gather (no sync
// A/B/C), in-place pre-merge, separate red. warp w owns k-chunk
// [128w,128w+128); producers jg = 4w..4w+3. Thread = 8j x 8b over 16 k.
// ---------------------------------------------------------------------------
__global__ void __launch_bounds__(NTHREADS, 1)
esn_scan_kernel(const float* __restrict__ W, float* __restrict__ out)
{
    extern __shared__ unsigned char smem_raw[];
    Smem& sm = *reinterpret_cast<Smem*>(smem_raw);

    const int tid  = threadIdx.x;
    const int lane = tid & 31;
    const int wrp  = tid >> 5;          // warp / k-chunk 0..7
    const int jt   = lane & 3;          // j-octet
    const int sv   = lane >> 2;         // sub-slice 0..7
    const int grp  = blockIdx.x & (NBG - 1);
    const int jg   = blockIdx.x >> 2;
    const int b0   = grp * BTILE;
    const int j0   = jg * JTILE;

    const int eb = tid >> 5;            // epilogue batch row 0..7
    const int ej = lane;                // epilogue j within tile

    // one-time W slice: Ws[k*36 + jl] = W[j0+jl][k]
    {
        const int jl = tid & 31;
        for (int k4 = tid >> 5; k4 < Hv / 4; k4 += 8) {
            float4 v = *(const float4*)&W[(size_t)(j0 + jl) * Hv + k4 * 4];
            sm.Ws[(k4 * 4 + 0) * WS + jl] = v.x;
            sm.Ws[(k4 * 4 + 1) * WS + jl] = v.y;
            sm.Ws[(k4 * 4 + 2) * WS + jl] = v.z;
            sm.Ws[(k4 * 4 + 3) * WS + jl] = v.w;
        }
    }

    // GEMM base: k = wrp*128 + sv + 8*i
    const unsigned ws_s = (unsigned)__cvta_generic_to_shared(sm.Ws)
                          + ((wrp * 128 + sv) * WS + jt * 8) * 4;
    const unsigned hs_base = (unsigned)__cvta_generic_to_shared(sm.h_s);
    const unsigned hs_s = hs_base + (wrp * 128 + sv) * HS * 4;

    __syncthreads();

    const float lr  = 0.9f;
    const float olr = 1.0f - lr;
    float hprev;

    // ---- peeled t = 0: no GEMM ----
    {
        const float u0 = out[((size_t)(b0 + eb) * Tv + 0) * Hv + j0 + ej];
        float th;
        asm("tanh.approx.f32 %0, %1;" : "=f"(th) : "f"(u0));
        const float hnew = lr * th;
        hprev = hnew;
        out[((size_t)(b0 + eb) * Tv + 0) * Hv + j0 + ej] = hnew;
        h_bufT[0][grp][(j0 + ej) * HS + eb] = hnew;
        __syncthreads();
        if (tid == 0)
            asm volatile("st.release.gpu.global.u32 [%0],%1;"
                         :: "l"(&g_flag[grp][jg][0]), "r"(1u));
    }

    for (int t = 1; t < Tv; ++t) {
        // prefetch u_in (read-once stream)
        float u0;
        {
            const float* up = &out[((size_t)(b0 + eb) * Tv + t) * Hv + j0 + ej];
            asm("ld.global.cs.f32 %0,[%1];" : "=f"(u0) : "l"(up));
        }

        // per-warp wait: lanes 0-3 poll the 4 producers of this chunk
        if (lane < 4) {
            const unsigned* fp = &g_flag[grp][4 * wrp + lane][0];
            unsigned v;
            do {
                asm volatile("ld.acquire.gpu.global.u32 %0,[%1];"
                             : "=r"(v) : "l"(fp));
            } while (v < (unsigned)t);
        }
        __syncwarp();

        // per-warp gather: own 5120B chunk (only warp w touches chunk w)
        {
            const char* src =
                (const char*)&h_bufT[(t - 1) & 1][grp][wrp * 128 * HS];
            const unsigned dst = hs_base + wrp * 128 * HS * 4;
            #pragma unroll
            for (int i = 0; i < 10; ++i) {
                int off = (lane + 32 * i) * 16;
                asm volatile("cp.async.cg.shared.global [%0], [%1], 16;"
                             :: "r"(dst + off), "l"(src + off));
            }
            asm volatile("cp.async.commit_group;");
            asm volatile("cp.async.wait_group 0;" ::: "memory");
        }
        __syncwarp();

        // GEMM over own chunk: per k = 2 LDS.128 (8 W) + 4 LDS.64 (8 h)
        unsigned long long a[4][8];
        #pragma unroll
        for (int q = 0; q < 4; ++q)
            #pragma unroll
            for (int b = 0; b < 8; ++b) a[q][b] = 0ull;

        {
            unsigned wa = ws_s, ha = hs_s;
            #pragma unroll
            for (int i = 0; i < KPT; ++i) {
                unsigned long long w01, w23, w45, w67;
                float h0, h1, h2, h3, h4, h5, h6, h7;
                asm("ld.shared.v2.u64 {%0,%1},[%2];"
                    : "=l"(w01), "=l"(w23) : "r"(wa));
                asm("ld.shared.v2.u64 {%0,%1},[%2+16];"
                    : "=l"(w45), "=l"(w67) : "r"(wa));
                asm("ld.shared.v2.f32 {%0,%1},[%2];"    : "=f"(h0), "=f"(h1) : "r"(ha));
                asm("ld.shared.v2.f32 {%0,%1},[%2+8];"  : "=f"(h2), "=f"(h3) : "r"(ha));
                asm("ld.shared.v2.f32 {%0,%1},[%2+16];" : "=f"(h4), "=f"(h5) : "r"(ha));
                asm("ld.shared.v2.f32 {%0,%1},[%2+24];" : "=f"(h6), "=f"(h7) : "r"(ha));
                float hv[8] = {h0, h1, h2, h3, h4, h5, h6, h7};
                #pragma unroll
                for (int b = 0; b < 8; ++b) {
                    unsigned long long hd;
                    asm("mov.b64 %0,{%1,%1};" : "=l"(hd) : "f"(hv[b]));
                    asm("fma.rn.f32x2 %0,%1,%2,%0;" : "+l"(a[0][b]) : "l"(w01), "l"(hd));
                    asm("fma.rn.f32x2 %0,%1,%2,%0;" : "+l"(a[1][b]) : "l"(w23), "l"(hd));
                    asm("fma.rn.f32x2 %0,%1,%2,%0;" : "+l"(a[2][b]) : "l"(w45), "l"(hd));
                    asm("fma.rn.f32x2 %0,%1,%2,%0;" : "+l"(a[3][b]) : "l"(w67), "l"(hd));
                }
                wa += 8 * WS * 4;
                ha += 8 * HS * 4;
            }
        }

        // in-place pre-merge: lane L += lane L^16 (slices sv and sv^4)
        #pragma unroll
        for (int q = 0; q < 4; ++q) {
            #pragma unroll
            for (int b = 0; b < 8; ++b) {
                unsigned long long o = __shfl_xor_sync(0xffffffffu, a[q][b], 16);
                asm("add.rn.f32x2 %0,%0,%1;" : "+l"(a[q][b]) : "l"(o));
            }
        }

        // merged partials: only sv<4 lanes store; slice id ms = wrp*4 + sv
        // (red writes at t are ordered after reduce reads at t-1 by sync E)
        if (sv < 4) {
            const int ms = wrp * 4 + sv;
            #pragma unroll
            for (int b = 0; b < 8; ++b) {
                float x0, y0, x1, y1, x2, y2, x3, y3;
                asm("mov.b64 {%0,%1},%2;" : "=f"(x0), "=f"(y0) : "l"(a[0][b]));
                asm("mov.b64 {%0,%1},%2;" : "=f"(x1), "=f"(y1) : "l"(a[1][b]));
                asm("mov.b64 {%0,%1},%2;" : "=f"(x2), "=f"(y2) : "l"(a[2][b]));
                asm("mov.b64 {%0,%1},%2;" : "=f"(x3), "=f"(y3) : "l"(a[3][b]));
                float* rp = &sm.red[ms * RS + b * 36 + jt * 8];
                *(float4*)(rp)     = make_float4(x0, y0, x1, y1);
                *(float4*)(rp + 4) = make_float4(x2, y2, x3, y3);
            }
        }
        __syncthreads();   // (D) red ready

        // reduce 32 merged slices with 4-way ILP (b=eb, j=ej)
        float ssum;
        {
            const float* rp = &sm.red[eb * 36 + ej];
            float s0 = 0.f, s1 = 0.f, s2 = 0.f, s3 = 0.f;
            #pragma unroll
            for (int s = 0; s < NMS; s += 4) {
                s0 += rp[(s + 0) * RS];
                s1 += rp[(s + 1) * RS];
                s2 += rp[(s + 2) * RS];
                s3 += rp[(s + 3) * RS];
            }
            ssum = (s0 + s1) + (s2 + s3);
        }

        // epilogue: h_new = 0.1*h + 0.9*tanh(u_in + h@W^T)
        const float u = u0 + ssum;
        float th;
        asm("tanh.approx.f32 %0, %1;" : "=f"(th) : "f"(u));
        const float hnew = olr * hprev + lr * th;
        hprev = hnew;

        {
            float* op = &out[((size_t)(b0 + eb) * Tv + t) * Hv + j0 + ej];
            asm volatile("st.global.cs.f32 [%0], %1;" :: "l"(op), "f"(hnew));
        }
        h_bufT[t & 1][grp][(j0 + ej) * HS + eb] = hnew;

        __syncthreads();   // (E) publish + reduce reads done
        if (tid == 0)
            asm volatile("st.release.gpu.global.u32 [%0],%1;"
                         :: "l"(&g_flag[grp][jg][0]), "r"((unsigned)(t + 1)));
    }
}

extern "C" void kernel_launch(void* const* d_in, const int* in_sizes, int n_in,
                              void* d_out, int out_size)
{
    const float* x   = (const float*)d_in[0];  // [32,1000,64]
    const float* Wiw = (const float*)d_in[1];  // [1024,64]
    const float* Wib = (const float*)d_in[2];  // [1024]
    const float* W   = (const float*)d_in[3];  // [1024,1024]
    float* out = (float*)d_out;                // [32,1000,1024]

    cudaFuncSetAttribute(esn_uin_kernel,
                         cudaFuncAttributeMaxDynamicSharedMemorySize,
                         (int)sizeof(UinSmem));
    cudaFuncSetAttribute(esn_scan_kernel,
                         cudaFuncAttributeMaxDynamicSharedMemorySize,
                         (int)sizeof(Smem));

    esn_uin_kernel<<<(Bv * Tv) / 64, 256, sizeof(UinSmem)>>>(x, Wiw, Wib, out);
    esn_scan_kernel<<<GRID, NTHREADS, sizeof(Smem)>>>(W, out);
}

// round 16
// speedup vs baseline: 3.2070x; 3.2070x over previous
#include <cuda_runtime.h>

#define Bv 32
#define Tv 1000
#define DINv 64
#define Hv 1024

#define NBG 4
#define NJG 32
#define BTILE 8
#define JTILE 32
#define NTHREADS 256
#define GRID (NBG * NJG)     // 128 CTAs, 1/SM

#define WS 36                // W row stride (floats)
#define HS 10                // h row stride (floats)
#define RS 296               // red slice stride (floats): 1184B -> 4-wf STS.128
#define NMS 32               // merged k-slices (64 pre-merged in-warp to 32)
#define KPT 16               // k per thread (strided by 64)

#define XSS 132              // uin tile stride (floats): 528B, 16B-multiple

__device__ unsigned int g_bar[4 * 64];          // per-group counters, 256B apart
__device__ float h_bufT[2][NBG][Hv * HS];       // h state, pre-laid-out [k*10+b]

struct Smem {
    float Ws[Hv * WS];                  // 147456 B
    union {
        float h_s[Hv * HS];             // 40960 B (live: gather -> end of GEMM)
        float red[NMS * RS];            // 37888 B (live: after GEMM -> reduce)
    } u;
};
// total = 188416 B

struct UinSmem {
    float xs[DINv * XSS];               // [k][r], r<128 : 33792 B
    float ws[DINv * XSS];               // [k][j], j<128 : 33792 B
};
// total = 67584 B

// ---------------------------------------------------------------------------
// Phase 1 (v2): u_in = x @ W_in^T + b -> out ; resets step counters.
// Register-blocked GEMM: block = 128 rows x 128 j, K=64; thread = 8r x 8j.
// Per warp-k: 6 smem wavefronts for 2048 MACs (341 MAC/wf). FFMA2-bound.
// ---------------------------------------------------------------------------
__global__ void __launch_bounds__(256)
esn_uin_kernel(const float* __restrict__ x, const float* __restrict__ Wiw,
               const float* __restrict__ Wib, float* __restrict__ out)
{
    extern __shared__ unsigned char usmem_raw[];
    UinSmem& us = *reinterpret_cast<UinSmem*>(usmem_raw);

    if (blockIdx.x == 0 && threadIdx.x < 4) g_bar[threadIdx.x * 64] = 0u;

    const int tid = threadIdx.x;
    const int rc  = blockIdx.x >> 3;          // row chunk 0..249
    const int jc  = blockIdx.x & 7;           // j chunk 0..7
    const int R0  = rc * 128;                 // (b,t) flattened row base
    const int J0  = jc * 128;

    // stage x tile transposed: xs[k][r] = x[(R0+r)*64 + k]
    {
        const int r  = tid >> 1;
        const int k0 = (tid & 1) * 32;
        const float4* xp = (const float4*)&x[(size_t)(R0 + r) * DINv + k0];
        #pragma unroll
        for (int q = 0; q < 8; ++q) {
            float4 v = xp[q];
            int k = k0 + q * 4;
            us.xs[(k + 0) * XSS + r] = v.x;
            us.xs[(k + 1) * XSS + r] = v.y;
            us.xs[(k + 2) * XSS + r] = v.z;
            us.xs[(k + 3) * XSS + r] = v.w;
        }
    }
    // stage W tile transposed: ws[k][j] = Wiw[(J0+j)*64 + k]
    {
        const int j  = tid >> 1;
        const int k0 = (tid & 1) * 32;
        const float4* wp = (const float4*)&Wiw[(size_t)(J0 + j) * DINv + k0];
        #pragma unroll
        for (int q = 0; q < 8; ++q) {
            float4 v = wp[q];
            int k = k0 + q * 4;
            us.ws[(k + 0) * XSS + j] = v.x;
            us.ws[(k + 1) * XSS + j] = v.y;
            us.ws[(k + 2) * XSS + j] = v.z;
            us.ws[(k + 3) * XSS + j] = v.w;
        }
    }
    __syncthreads();

    const int ro = tid >> 4;                  // row octet 0..15
    const int jo = tid & 15;                  // j octet 0..15

    // bias into accumulator init (j-pairs)
    unsigned long long b2[4];
    #pragma unroll
    for (int p = 0; p < 4; ++p) {
        float2 bb = *(const float2*)&Wib[J0 + jo * 8 + 2 * p];
        asm("mov.b64 %0,{%1,%2};" : "=l"(b2[p]) : "f"(bb.x), "f"(bb.y));
    }
    unsigned long long acc[8][4];
    #pragma unroll
    for (int r = 0; r < 8; ++r)
        #pragma unroll
        for (int p = 0; p < 4; ++p) acc[r][p] = b2[p];

    unsigned wa = (unsigned)__cvta_generic_to_shared(us.ws) + (jo * 8) * 4;
    unsigned xa = (unsigned)__cvta_generic_to_shared(us.xs) + (ro * 8) * 4;

    #pragma unroll 8
    for (int k = 0; k < DINv; ++k) {
        unsigned long long w0, w1, w2, w3;
        float x0, x1, x2, x3, x4, x5, x6, x7;
        asm("ld.shared.v2.u64 {%0,%1},[%2];"    : "=l"(w0), "=l"(w1) : "r"(wa));
        asm("ld.shared.v2.u64 {%0,%1},[%2+16];" : "=l"(w2), "=l"(w3) : "r"(wa));
        asm("ld.shared.v4.f32 {%0,%1,%2,%3},[%4];"
            : "=f"(x0), "=f"(x1), "=f"(x2), "=f"(x3) : "r"(xa));
        asm("ld.shared.v4.f32 {%0,%1,%2,%3},[%4+16];"
            : "=f"(x4), "=f"(x5), "=f"(x6), "=f"(x7) : "r"(xa));
        float xv[8] = {x0, x1, x2, x3, x4, x5, x6, x7};
        #pragma unroll
        for (int r = 0; r < 8; ++r) {
            unsigned long long xd;
            asm("mov.b64 %0,{%1,%1};" : "=l"(xd) : "f"(xv[r]));
            asm("fma.rn.f32x2 %0,%1,%2,%0;" : "+l"(acc[r][0]) : "l"(w0), "l"(xd));
            asm("fma.rn.f32x2 %0,%1,%2,%0;" : "+l"(acc[r][1]) : "l"(w1), "l"(xd));
            asm("fma.rn.f32x2 %0,%1,%2,%0;" : "+l"(acc[r][2]) : "l"(w2), "l"(xd));
            asm("fma.rn.f32x2 %0,%1,%2,%0;" : "+l"(acc[r][3]) : "l"(w3), "l"(xd));
        }
        wa += XSS * 4;
        xa += XSS * 4;
    }

    // store: 4 x 8B per row (raw packed pairs)
    {
        float* orow = &out[(size_t)(R0 + ro * 8) * Hv + J0 + jo * 8];
        #pragma unroll
        for (int r = 0; r < 8; ++r) {
            unsigned long long* op = (unsigned long long*)(orow + (size_t)r * Hv);
            op[0] = acc[r][0];
            op[1] = acc[r][1];
            op[2] = acc[r][2];
            op[3] = acc[r][3];
        }
    }
}

// ---------------------------------------------------------------------------
// Phase 2: persistent scan (R14 EXACT — measured best 3.418us/step).
// 256 threads; thread = 8j x 8b block over 16 strided k; counter barrier;
// CTA-wide cp.async gather; in-place shfl pre-merge; NMS=32 reduce.
// ---------------------------------------------------------------------------
__global__ void __launch_bounds__(NTHREADS, 1)
esn_scan_kernel(const float* __restrict__ W, float* __restrict__ out)
{
    extern __shared__ unsigned char smem_raw[];
    Smem& sm = *reinterpret_cast<Smem*>(smem_raw);

    const int tid  = threadIdx.x;
    const int lane = tid & 31;
    const int jt   = tid & 3;           // j-octet: j = jt*8 .. jt*8+7
    const int ks   = tid >> 2;          // k-slice 0..63 (k = ks + 64*i)
    const int wrp  = tid >> 5;          // warp id
    const int sv   = (tid >> 2) & 7;    // sub-slice within warp
    const int grp  = blockIdx.x & (NBG - 1);
    const int jg   = blockIdx.x >> 2;
    const int b0   = grp * BTILE;
    const int j0   = jg * JTILE;
    unsigned* bar  = &g_bar[grp * 64];

    const int eb = tid >> 5;            // epilogue batch row 0..7
    const int ej = lane;                // epilogue j within tile

    // one-time W slice: Ws[k*36 + jl] = W[j0+jl][k]
    {
        const int jl = tid & 31;
        for (int k4 = tid >> 5; k4 < Hv / 4; k4 += 8) {
            float4 v = *(const float4*)&W[(size_t)(j0 + jl) * Hv + k4 * 4];
            sm.Ws[(k4 * 4 + 0) * WS + jl] = v.x;
            sm.Ws[(k4 * 4 + 1) * WS + jl] = v.y;
            sm.Ws[(k4 * 4 + 2) * WS + jl] = v.z;
            sm.Ws[(k4 * 4 + 3) * WS + jl] = v.w;
        }
    }

    const unsigned ws_s = (unsigned)__cvta_generic_to_shared(sm.Ws)
                          + (ks * WS + jt * 8) * 4;
    const unsigned hs_s = (unsigned)__cvta_generic_to_shared(sm.u.h_s)
                          + (ks * HS) * 4;
    const unsigned hs_base = (unsigned)__cvta_generic_to_shared(sm.u.h_s);

    __syncthreads();

    const float lr  = 0.9f;
    const float olr = 1.0f - lr;
    float hprev;

    // ---- peeled t = 0: no GEMM ----
    {
        const float u0 = out[((size_t)(b0 + eb) * Tv + 0) * Hv + j0 + ej];
        float th;
        asm("tanh.approx.f32 %0, %1;" : "=f"(th) : "f"(u0));
        const float hnew = lr * th;
        hprev = hnew;
        out[((size_t)(b0 + eb) * Tv + 0) * Hv + j0 + ej] = hnew;
        h_bufT[0][grp][(j0 + ej) * HS + eb] = hnew;
        __syncthreads();
        if (tid == 0)
            asm volatile("red.release.gpu.global.add.u32 [%0], 1;" :: "l"(bar));
    }

    for (int t = 1; t < Tv; ++t) {
        // prefetch u_in (read-once stream)
        float u0;
        {
            const float* up = &out[((size_t)(b0 + eb) * Tv + t) * Hv + j0 + ej];
            asm("ld.global.cs.f32 %0,[%1];" : "=f"(u0) : "l"(up));
        }

        // distributed group barrier: every thread polls (1 coalesced req/warp)
        {
            const unsigned tgt = (unsigned)t * NJG;
            unsigned v;
            do {
                asm volatile("ld.acquire.gpu.global.u32 %0, [%1];"
                             : "=r"(v) : "l"(bar));
            } while (v < tgt);
        }

        // gather: 40KB linear copy via cp.async
        {
            const char* src = (const char*)&h_bufT[(t - 1) & 1][grp][0];
            #pragma unroll
            for (int i = 0; i < 10; ++i) {
                int off = (tid + i * NTHREADS) * 16;
                asm volatile("cp.async.cg.shared.global [%0], [%1], 16;"
                             :: "r"(hs_base + off), "l"(src + off));
            }
            asm volatile("cp.async.commit_group;");
            asm volatile("cp.async.wait_group 0;" ::: "memory");
        }
        __syncthreads();   // (B) h_s ready

        // GEMM: per k = 2 LDS.128 (8 W) + 4 LDS.64 (8 h) + 8 dup + 32 FFMA2
        unsigned long long a[4][8];
        #pragma unroll
        for (int q = 0; q < 4; ++q)
            #pragma unroll
            for (int b = 0; b < 8; ++b) a[q][b] = 0ull;

        {
            unsigned wa = ws_s, ha = hs_s;
            #pragma unroll
            for (int i = 0; i < KPT; ++i) {
                unsigned long long w01, w23, w45, w67;
                float h0, h1, h2, h3, h4, h5, h6, h7;
                asm("ld.shared.v2.u64 {%0,%1},[%2];"
                    : "=l"(w01), "=l"(w23) : "r"(wa));
                asm("ld.shared.v2.u64 {%0,%1},[%2+16];"
                    : "=l"(w45), "=l"(w67) : "r"(wa));
                asm("ld.shared.v2.f32 {%0,%1},[%2];"    : "=f"(h0), "=f"(h1) : "r"(ha));
                asm("ld.shared.v2.f32 {%0,%1},[%2+8];"  : "=f"(h2), "=f"(h3) : "r"(ha));
                asm("ld.shared.v2.f32 {%0,%1},[%2+16];" : "=f"(h4), "=f"(h5) : "r"(ha));
                asm("ld.shared.v2.f32 {%0,%1},[%2+24];" : "=f"(h6), "=f"(h7) : "r"(ha));
                float hv[8] = {h0, h1, h2, h3, h4, h5, h6, h7};
                #pragma unroll
                for (int b = 0; b < 8; ++b) {
                    unsigned long long hd;
                    asm("mov.b64 %0,{%1,%1};" : "=l"(hd) : "f"(hv[b]));
                    asm("fma.rn.f32x2 %0,%1,%2,%0;" : "+l"(a[0][b]) : "l"(w01), "l"(hd));
                    asm("fma.rn.f32x2 %0,%1,%2,%0;" : "+l"(a[1][b]) : "l"(w23), "l"(hd));
                    asm("fma.rn.f32x2 %0,%1,%2,%0;" : "+l"(a[2][b]) : "l"(w45), "l"(hd));
                    asm("fma.rn.f32x2 %0,%1,%2,%0;" : "+l"(a[3][b]) : "l"(w67), "l"(hd));
                }
                wa += 64 * WS * 4;
                ha += 64 * HS * 4;
            }
        }

        // in-place pre-merge: lane L += lane L^16 (slices sv and sv^4)
        #pragma unroll
        for (int q = 0; q < 4; ++q) {
            #pragma unroll
            for (int b = 0; b < 8; ++b) {
                unsigned long long o = __shfl_xor_sync(0xffffffffu, a[q][b], 16);
                asm("add.rn.f32x2 %0,%0,%1;" : "+l"(a[q][b]) : "l"(o));
            }
        }

        __syncthreads();   // (C) h_s reads done before red overwrite (union)

        // merged partials: only sv<4 lanes store; slice id ms = wrp*4 + sv
        if (sv < 4) {
            const int ms = wrp * 4 + sv;
            #pragma unroll
            for (int b = 0; b < 8; ++b) {
                float x0, y0, x1, y1, x2, y2, x3, y3;
                asm("mov.b64 {%0,%1},%2;" : "=f"(x0), "=f"(y0) : "l"(a[0][b]));
                asm("mov.b64 {%0,%1},%2;" : "=f"(x1), "=f"(y1) : "l"(a[1][b]));
                asm("mov.b64 {%0,%1},%2;" : "=f"(x2), "=f"(y2) : "l"(a[2][b]));
                asm("mov.b64 {%0,%1},%2;" : "=f"(x3), "=f"(y3) : "l"(a[3][b]));
                float* rp = &sm.u.red[ms * RS + b * 36 + jt * 8];
                *(float4*)(rp)     = make_float4(x0, y0, x1, y1);
                *(float4*)(rp + 4) = make_float4(x2, y2, x3, y3);
            }
        }
        __syncthreads();   // (D) red ready

        // reduce 32 merged slices with 4-way ILP (b=eb, j=ej)
        float ssum;
        {
            const float* rp = &sm.u.red[eb * 36 + ej];
            float s0 = 0.f, s1 = 0.f, s2 = 0.f, s3 = 0.f;
            #pragma unroll
            for (int s = 0; s < NMS; s += 4) {
                s0 += rp[(s + 0) * RS];
                s1 += rp[(s + 1) * RS];
                s2 += rp[(s + 2) * RS];
                s3 += rp[(s + 3) * RS];
            }
            ssum = (s0 + s1) + (s2 + s3);
        }

        // epilogue: h_new = 0.1*h + 0.9*tanh(u_in + h@W^T)
        const float u = u0 + ssum;
        float th;
        asm("tanh.approx.f32 %0, %1;" : "=f"(th) : "f"(u));
        const float hnew = olr * hprev + lr * th;
        hprev = hnew;

        {
            float* op = &out[((size_t)(b0 + eb) * Tv + t) * Hv + j0 + ej];
            asm volatile("st.global.cs.f32 [%0], %1;" :: "l"(op), "f"(hnew));
        }
        h_bufT[t & 1][grp][(j0 + ej) * HS + eb] = hnew;

        __syncthreads();   // (E) publish + red reads done
        if (tid == 0)
            asm volatile("red.release.gpu.global.add.u32 [%0], 1;" :: "l"(bar));
    }
}

extern "C" void kernel_launch(void* const* d_in, const int* in_sizes, int n_in,
                              void* d_out, int out_size)
{
    const float* x   = (const float*)d_in[0];  // [32,1000,64]
    const float* Wiw = (const float*)d_in[1];  // [1024,64]
    const float* Wib = (const float*)d_in[2];  // [1024]
    const float* W   = (const float*)d_in[3];  // [1024,1024]
    float* out = (float*)d_out;                // [32,1000,1024]

    cudaFuncSetAttribute(esn_uin_kernel,
                         cudaFuncAttributeMaxDynamicSharedMemorySize,
                         (int)sizeof(UinSmem));
    cudaFuncSetAttribute(esn_scan_kernel,
                         cudaFuncAttributeMaxDynamicSharedMemorySize,
                         (int)sizeof(Smem));

    // 250 row-chunks x 8 j-chunks = 2000 blocks (32000 rows = 250*128 exactly)
    esn_uin_kernel<<<2000, 256, sizeof(UinSmem)>>>(x, Wiw, Wib, out);
    esn_scan_kernel<<<GRID, NTHREADS, sizeof(Smem)>>>(W, out);
}